// round 5
// baseline (speedup 1.0000x reference)
#include <cuda_runtime.h>
#include <cstdint>

// Problem constants
constexpr int T_PTS = 8192;
constexpr int D_DIM = 512;
constexpr int N_SYN = 4;

// GEMM tiling
constexpr int BM = 128;
constexpr int BN = 128;
constexpr int BK = 8;
constexpr int JSPLIT = 4;
constexpr int JCHUNK = T_PTS / JSPLIT;   // 2048
constexpr int JTILES = JCHUNK / BN;      // 16
constexpr int KTILES = D_DIM / BK;       // 64

// Scratch (device globals; no allocations allowed)
__device__ float g_sq[T_PTS];
__device__ float g_pv[T_PTS * JSPLIT * 4];
__device__ int   g_pi[T_PTS * JSPLIT * 4];
__device__ int   g_neigh[T_PTS * N_SYN];

// ---------------------------------------------------------------------------
// 1) squared norms: one warp per row
// ---------------------------------------------------------------------------
__global__ void sq_kernel(const float* __restrict__ X) {
    int warp = (blockIdx.x * blockDim.x + threadIdx.x) >> 5;
    int lane = threadIdx.x & 31;
    if (warp >= T_PTS) return;
    const float4* X4 = (const float4*)X;
    float s = 0.f;
#pragma unroll
    for (int q = 0; q < 4; q++) {
        float4 v = X4[warp * (D_DIM / 4) + q * 32 + lane];
        s = fmaf(v.x, v.x, s);
        s = fmaf(v.y, v.y, s);
        s = fmaf(v.z, v.z, s);
        s = fmaf(v.w, v.w, s);
    }
#pragma unroll
    for (int off = 16; off; off >>= 1) s += __shfl_xor_sync(0xffffffffu, s, off);
    if (lane == 0) g_sq[warp] = s;
}

// Ordering comparator with index tie-break (matches jax top_k stability)
__device__ __forceinline__ bool lessc(float va, int ia, float vb, int ib) {
    return (va < vb) || (va == vb && ia < ib);
}

// ---------------------------------------------------------------------------
// 2) fused GEMM + per-row top-4 (by sq_j - 2*dot, self excluded)
//    grid = (T/BM, JSPLIT), 256 threads, 8x8 frags
// ---------------------------------------------------------------------------
__global__ void __launch_bounds__(256, 1)
gemm_topk_kernel(const float* __restrict__ X) {
    __shared__ float As[BK][BM];
    __shared__ float Bs[BK][BN];

    const int tid = threadIdx.x;
    const int tx = tid & 15;        // column-thread 0..15
    const int ty = tid >> 4;        // row-thread 0..15
    const int rm = blockIdx.x * BM;
    const int jb = blockIdx.y * JCHUNK;

    // global-load mapping: each thread loads one float4 per tile per matrix
    const int lr = tid >> 1;            // 0..127
    const int lc = (tid & 1) * 4;       // 0 or 4

    // running top-4 per owned row
    float tv[8][4];
    int   ti[8][4];
#pragma unroll
    for (int m = 0; m < 8; m++)
#pragma unroll
        for (int r = 0; r < 4; r++) { tv[m][r] = 3.0e38f; ti[m][r] = 0x7fffffff; }

    const float* Aptr = X + (rm + lr) * D_DIM + lc;

    for (int jt = 0; jt < JTILES; jt++) {
        float acc[8][8];
#pragma unroll
        for (int m = 0; m < 8; m++)
#pragma unroll
            for (int n = 0; n < 8; n++) acc[m][n] = 0.f;

        const int jrow = jb + jt * BN + lr;
        const float* Bptr = X + jrow * D_DIM + lc;

        float4 aReg = *(const float4*)(Aptr);
        float4 bReg = *(const float4*)(Bptr);

        for (int kt = 0; kt < KTILES; kt++) {
            __syncthreads();
            As[lc + 0][lr] = aReg.x; As[lc + 1][lr] = aReg.y;
            As[lc + 2][lr] = aReg.z; As[lc + 3][lr] = aReg.w;
            Bs[lc + 0][lr] = bReg.x; Bs[lc + 1][lr] = bReg.y;
            Bs[lc + 2][lr] = bReg.z; Bs[lc + 3][lr] = bReg.w;
            __syncthreads();
            if (kt + 1 < KTILES) {
                aReg = *(const float4*)(Aptr + (kt + 1) * BK);
                bReg = *(const float4*)(Bptr + (kt + 1) * BK);
            }
#pragma unroll
            for (int k = 0; k < BK; k++) {
                float a[8], b[8];
                *(float4*)&a[0] = *(const float4*)&As[k][ty * 8];
                *(float4*)&a[4] = *(const float4*)&As[k][ty * 8 + 4];
                // split b columns {tx*4 .. +3} and {64 + tx*4 .. +3} -> conflict-free
                *(float4*)&b[0] = *(const float4*)&Bs[k][tx * 4];
                *(float4*)&b[4] = *(const float4*)&Bs[k][64 + tx * 4];
#pragma unroll
                for (int m = 0; m < 8; m++)
#pragma unroll
                    for (int n = 0; n < 8; n++)
                        acc[m][n] = fmaf(a[m], b[n], acc[m][n]);
            }
        }

        // epilogue: key = sq_j - 2*dot ; update top-4 with index tie-break
        int jcol[8];
#pragma unroll
        for (int n = 0; n < 8; n++)
            jcol[n] = jb + jt * BN + ((n < 4) ? (tx * 4 + n) : (64 + tx * 4 + n - 4));
        float sj[8];
#pragma unroll
        for (int n = 0; n < 8; n++) sj[n] = g_sq[jcol[n]];

#pragma unroll
        for (int m = 0; m < 8; m++) {
            const int irow = rm + ty * 8 + m;
#pragma unroll
            for (int n = 0; n < 8; n++) {
                const int j = jcol[n];
                const float key = fmaf(-2.f, acc[m][n], sj[n]);
                if (j != irow && lessc(key, j, tv[m][3], ti[m][3])) {
                    tv[m][3] = key; ti[m][3] = j;
#pragma unroll
                    for (int r = 3; r > 0; r--) {
                        if (lessc(tv[m][r], ti[m][r], tv[m][r - 1], ti[m][r - 1])) {
                            float fv = tv[m][r]; tv[m][r] = tv[m][r - 1]; tv[m][r - 1] = fv;
                            int   fi = ti[m][r]; ti[m][r] = ti[m][r - 1]; ti[m][r - 1] = fi;
                        }
                    }
                }
            }
        }
    }

    // butterfly merge across the 16 tx-threads sharing each row (lane bits 0..3)
#pragma unroll
    for (int mask = 1; mask <= 8; mask <<= 1) {
#pragma unroll
        for (int m = 0; m < 8; m++) {
            float ov[4]; int oi[4];
#pragma unroll
            for (int r = 0; r < 4; r++) {
                ov[r] = __shfl_xor_sync(0xffffffffu, tv[m][r], mask);
                oi[r] = __shfl_xor_sync(0xffffffffu, ti[m][r], mask);
            }
#pragma unroll
            for (int r = 0; r < 4; r++) {
                if (lessc(ov[r], oi[r], tv[m][3], ti[m][3])) {
                    tv[m][3] = ov[r]; ti[m][3] = oi[r];
#pragma unroll
                    for (int q = 3; q > 0; q--) {
                        if (lessc(tv[m][q], ti[m][q], tv[m][q - 1], ti[m][q - 1])) {
                            float fv = tv[m][q]; tv[m][q] = tv[m][q - 1]; tv[m][q - 1] = fv;
                            int   fi = ti[m][q]; ti[m][q] = ti[m][q - 1]; ti[m][q - 1] = fi;
                        }
                    }
                }
            }
        }
    }

    if (tx == 0) {
#pragma unroll
        for (int m = 0; m < 8; m++) {
            const int row = rm + ty * 8 + m;
            const int base = (row * JSPLIT + blockIdx.y) * 4;
#pragma unroll
            for (int r = 0; r < 4; r++) {
                g_pv[base + r] = tv[m][r];
                g_pi[base + r] = ti[m][r];
            }
        }
    }
}

// ---------------------------------------------------------------------------
// 3) merge JSPLIT partial top-4 lists -> final 4 neighbors, ascending distance
// ---------------------------------------------------------------------------
__global__ void merge_kernel() {
    int t = blockIdx.x * blockDim.x + threadIdx.x;
    if (t >= T_PTS) return;
    float tv[4]; int ti[4];
#pragma unroll
    for (int r = 0; r < 4; r++) { tv[r] = 3.0e38f; ti[r] = 0x7fffffff; }
    for (int s = 0; s < JSPLIT; s++) {
        const int base = (t * JSPLIT + s) * 4;
#pragma unroll
        for (int r = 0; r < 4; r++) {
            const float v = g_pv[base + r];
            const int   i = g_pi[base + r];
            if (lessc(v, i, tv[3], ti[3])) {
                tv[3] = v; ti[3] = i;
#pragma unroll
                for (int q = 3; q > 0; q--) {
                    if (lessc(tv[q], ti[q], tv[q - 1], ti[q - 1])) {
                        float fv = tv[q]; tv[q] = tv[q - 1]; tv[q - 1] = fv;
                        int   fi = ti[q]; ti[q] = ti[q - 1]; ti[q - 1] = fi;
                    }
                }
            }
        }
    }
#pragma unroll
    for (int r = 0; r < 4; r++) g_neigh[t * N_SYN + r] = ti[r];
}

// ---------------------------------------------------------------------------
// 4) gather + interpolate: out[(t*4+n)] = X[t] + gaps[t,n]*(X[sel]-X[t])
// ---------------------------------------------------------------------------
__global__ void interp_kernel(const float* __restrict__ X,
                              const float* __restrict__ gaps,
                              const int* __restrict__ nn_choice,
                              float* __restrict__ out) {
    const int gid = blockIdx.x * blockDim.x + threadIdx.x;   // float4 index
    const int row = gid >> 7;        // D/4 = 128 float4 per output row
    const int d4  = gid & 127;
    const int t   = row >> 2;        // row = t*4 + n
    const float g = gaps[row];
    const int   c = nn_choice[row];  // 0..3
    const int   s = g_neigh[t * N_SYN + c];
    const float4* X4 = (const float4*)X;
    const float4 x  = X4[t * 128 + d4];
    const float4 xs = X4[s * 128 + d4];
    float4 o;
    o.x = fmaf(g, xs.x - x.x, x.x);
    o.y = fmaf(g, xs.y - x.y, x.y);
    o.z = fmaf(g, xs.z - x.z, x.z);
    o.w = fmaf(g, xs.w - x.w, x.w);
    ((float4*)out)[gid] = o;
}

// ---------------------------------------------------------------------------
extern "C" void kernel_launch(void* const* d_in, const int* in_sizes, int n_in,
                              void* d_out, int out_size) {
    (void)in_sizes; (void)n_in; (void)out_size;
    const float* X    = (const float*)d_in[0];
    const float* gaps = (const float*)d_in[1];
    const int*   nnc  = (const int*)d_in[2];
    float* out = (float*)d_out;

    sq_kernel<<<T_PTS / 8, 256>>>(X);                       // 1024 blocks, warp/row
    dim3 grid(T_PTS / BM, JSPLIT);
    gemm_topk_kernel<<<grid, 256>>>(X);
    merge_kernel<<<T_PTS / 256, 256>>>();
    interp_kernel<<<(T_PTS * N_SYN * (D_DIM / 4)) / 256, 256>>>(X, gaps, nnc, out);
}

// round 8
// speedup vs baseline: 5.4451x; 5.4451x over previous
#include <cuda_runtime.h>
#include <cuda_bf16.h>
#include <cstdint>

// ==========================================================================
// Problem constants
// ==========================================================================
constexpr int T_PTS = 8192;
constexpr int D_DIM = 512;
constexpr int N_SYN = 4;

// GEMM tiling
constexpr int BM = 128;
constexpr int BN = 128;
constexpr int BK = 64;                   // bf16 K per B stage (128 bytes/row)
constexpr int JSPLIT = 2;
constexpr int JCHUNK = T_PTS / JSPLIT;   // 4096
constexpr int JTILES = JCHUNK / BN;      // 32
constexpr int KSTG = D_DIM / BK;         // 8 stages per j-tile
constexpr int STAGES = JTILES * KSTG;    // 256
constexpr int NCAND = 8;

// SMEM layout (dynamic)
constexpr int SM_A = 0;                          // 128 x 512 bf16 = 131072
constexpr int A_BYTES = BM * D_DIM * 2;
constexpr int SM_B0 = A_BYTES;                   // 131072
constexpr int B_BYTES = BN * BK * 2;             // 16384
constexpr int SM_B1 = SM_B0 + B_BYTES;           // 147456
constexpr int SM_SQ = SM_B1 + B_BYTES;           // 163840
constexpr int SM_SCR = SM_B0;                    // reused post-MMA (32KB avail)
constexpr int SMEM_TOTAL = SM_SQ + JCHUNK * 4;   // 180224

// ==========================================================================
// Device scratch
// ==========================================================================
__device__ float g_sq[T_PTS];
__device__ __nv_bfloat16 g_xbf[(size_t)T_PTS * D_DIM];
__device__ int g_cand[T_PTS * JSPLIT * NCAND];
__device__ int g_neigh[T_PTS * N_SYN];

// ==========================================================================
// PTX helpers (sm_80-compatible only — NO tcgen05/TMEM, harness PTX target
// is plain sm_103)
// ==========================================================================
__device__ __forceinline__ uint32_t smem_u32(const void* p) {
    uint32_t a;
    asm("{ .reg .u64 t; cvta.to.shared.u64 t, %1; cvt.u32.u64 %0, t; }"
        : "=r"(a) : "l"(p));
    return a;
}
#define CP_ASYNC16(dst, src) \
    asm volatile("cp.async.cg.shared.global [%0], [%1], 16;" :: "r"(dst), "l"(src))
#define CP_COMMIT() asm volatile("cp.async.commit_group;" ::: "memory")
#define CP_WAIT(n) asm volatile("cp.async.wait_group %0;" :: "n"(n) : "memory")

// NON-trans ldmatrix: correct for K-major (k-contiguous) A and B operands of
// mma .row.col — each 16B address points at 8 consecutive k elements.
#define LDSM_X4(r0, r1, r2, r3, addr) \
    asm volatile("ldmatrix.sync.aligned.m8n8.x4.shared.b16 {%0,%1,%2,%3}, [%4];" \
                 : "=r"(r0), "=r"(r1), "=r"(r2), "=r"(r3) : "r"(addr))

#define MMA16816(d, a, b) \
    asm volatile("mma.sync.aligned.m16n8k16.row.col.f32.bf16.bf16.f32 " \
                 "{%0,%1,%2,%3}, {%4,%5,%6,%7}, {%8,%9}, {%0,%1,%2,%3};" \
                 : "+f"((d)[0]), "+f"((d)[1]), "+f"((d)[2]), "+f"((d)[3]) \
                 : "r"((a)[0]), "r"((a)[1]), "r"((a)[2]), "r"((a)[3]), \
                   "r"((b)[0]), "r"((b)[1]))

// 128B-row SW128 swizzle (conflict-free ldmatrix)
__device__ __forceinline__ uint32_t sw128(uint32_t off) {
    return off ^ ((off >> 3) & 0x70);
}

// ==========================================================================
// 0) bf16 copy of X
// ==========================================================================
__global__ void prep_bf16(const float* __restrict__ X) {
    int i = blockIdx.x * blockDim.x + threadIdx.x;
    float4 v = ((const float4*)X)[i];
    ((__nv_bfloat162*)g_xbf)[i * 2 + 0] = __floats2bfloat162_rn(v.x, v.y);
    ((__nv_bfloat162*)g_xbf)[i * 2 + 1] = __floats2bfloat162_rn(v.z, v.w);
}

// ==========================================================================
// 1) squared norms
// ==========================================================================
__global__ void sq_kernel(const float* __restrict__ X) {
    int warp = (blockIdx.x * blockDim.x + threadIdx.x) >> 5;
    int lane = threadIdx.x & 31;
    if (warp >= T_PTS) return;
    const float4* X4 = (const float4*)X;
    float s = 0.f;
#pragma unroll
    for (int q = 0; q < 4; q++) {
        float4 v = X4[warp * (D_DIM / 4) + q * 32 + lane];
        s = fmaf(v.x, v.x, s); s = fmaf(v.y, v.y, s);
        s = fmaf(v.z, v.z, s); s = fmaf(v.w, v.w, s);
    }
#pragma unroll
    for (int off = 16; off; off >>= 1) s += __shfl_xor_sync(0xffffffffu, s, off);
    if (lane == 0) g_sq[warp] = s;
}

// ==========================================================================
// 2) mma.sync bf16 GEMM + approximate per-row candidates
// ==========================================================================
__device__ __forceinline__ void ins4(float key, int j, float* cv, int* ci) {
    cv[3] = key; ci[3] = j;
#pragma unroll
    for (int q = 3; q > 0; q--) {
        if (cv[q] < cv[q - 1]) {
            float tv = cv[q]; cv[q] = cv[q - 1]; cv[q - 1] = tv;
            int t2 = ci[q]; ci[q] = ci[q - 1]; ci[q - 1] = t2;
        }
    }
}
__device__ __forceinline__ void ins8(float key, int j, float* cv, int* ci) {
    cv[7] = key; ci[7] = j;
#pragma unroll
    for (int q = 7; q > 0; q--) {
        if (cv[q] < cv[q - 1]) {
            float tv = cv[q]; cv[q] = cv[q - 1]; cv[q - 1] = tv;
            int t2 = ci[q]; ci[q] = ci[q - 1]; ci[q - 1] = t2;
        }
    }
}

__global__ void __launch_bounds__(256, 1) gemm_topk() {
    extern __shared__ char smem[];
    const uint32_t sb = smem_u32(smem);
    const int tid = threadIdx.x;
    const int wid = tid >> 5;
    const int lane = tid & 31;
    const int g = lane >> 2;        // group row 0..7
    const int tq = lane & 3;        // quad thread 0..3
    const int wy = wid & 3;         // m-band (32 rows)
    const int wx = wid >> 2;        // n-band (64 cols)
    const int rm = blockIdx.x * BM;
    const int jb = blockIdx.y * JCHUNK;

    // ---- stage sq for this j-chunk ----
    for (int q = tid; q < JCHUNK; q += 256)
        *(float*)(smem + SM_SQ + q * 4) = g_sq[jb + q];

    // ---- async-load resident A tile [128 x 512] (swizzled per 64-col chunk) ----
    {
        const __nv_bfloat16* src = g_xbf + (size_t)rm * D_DIM;
#pragma unroll
        for (int it = 0; it < 32; it++) {
            int u = tid + it * 256;          // 16B chunk id, 64 per row
            int r = u >> 6, c = u & 63;      // c covers k = c*8..c*8+7
            uint32_t dst = sb + SM_A + (uint32_t)(c >> 3) * 16384u +
                           sw128((uint32_t)r * 128u + (uint32_t)(c & 7) * 16u);
            CP_ASYNC16(dst, src + (size_t)r * D_DIM + c * 8);
        }
    }
    CP_COMMIT();

    // ---- B stage loader ----
    auto load_b = [&](int s) {
        const int jt = s >> 3, kc = s & 7;
        const uint32_t boff = (s & 1) ? SM_B1 : SM_B0;
        const __nv_bfloat16* src =
            g_xbf + (size_t)(jb + jt * BN) * D_DIM + kc * BK;
#pragma unroll
        for (int it = 0; it < 4; it++) {
            int u = tid + it * 256;          // 16B chunk, 8 per row
            int r = u >> 3, c = u & 7;
            uint32_t dst = sb + boff +
                           sw128((uint32_t)r * 128u + (uint32_t)c * 16u);
            CP_ASYNC16(dst, src + (size_t)r * D_DIM + c * 8);
        }
        CP_COMMIT();
    };

    load_b(0);

    // running per-thread top-4 for 4 owned rows
    float tv[4][4]; int ti[4][4];
#pragma unroll
    for (int m = 0; m < 4; m++)
#pragma unroll
        for (int q = 0; q < 4; q++) { tv[m][q] = 3.0e38f; ti[m][q] = 0x7fffffff; }

    float acc[2][8][4];

#pragma unroll 1
    for (int s = 0; s < STAGES; s++) {
        if (s + 1 < STAGES) { load_b(s + 1); CP_WAIT(1); }
        else                { CP_WAIT(0); }
        __syncthreads();

        const int jt = s >> 3, kc = s & 7;
        const uint32_t boff = (s & 1) ? SM_B1 : SM_B0;

        if (kc == 0) {
#pragma unroll
            for (int mi = 0; mi < 2; mi++)
#pragma unroll
                for (int ni = 0; ni < 8; ni++)
#pragma unroll
                    for (int e = 0; e < 4; e++) acc[mi][ni][e] = 0.f;
        }

#pragma unroll
        for (int ks = 0; ks < 4; ks++) {
            uint32_t a[2][4];
#pragma unroll
            for (int mi = 0; mi < 2; mi++) {
                int r = wy * 32 + mi * 16 + (lane & 15);
                int ke = ks * 16 + ((lane & 16) >> 1);     // 0 or +8
                uint32_t addr = sb + SM_A + (uint32_t)kc * 16384u +
                                sw128((uint32_t)r * 128u + (uint32_t)ke * 2u);
                LDSM_X4(a[mi][0], a[mi][1], a[mi][2], a[mi][3], addr);
            }
            uint32_t b[8][2];
#pragma unroll
            for (int nb = 0; nb < 4; nb++) {
                int jr = wx * 64 + nb * 16 + ((lane & 16) >> 1) + (lane & 7);
                int ke = ks * 16 + (lane & 8);
                uint32_t addr = sb + boff +
                                sw128((uint32_t)jr * 128u + (uint32_t)ke * 2u);
                LDSM_X4(b[2 * nb][0], b[2 * nb][1],
                        b[2 * nb + 1][0], b[2 * nb + 1][1], addr);
            }
#pragma unroll
            for (int mi = 0; mi < 2; mi++)
#pragma unroll
                for (int ni = 0; ni < 8; ni++)
                    MMA16816(acc[mi][ni], a[mi], b[ni]);
        }

        if (kc == 7) {
            // epilogue for tile jt: key = sq_j - 2*dot, per-thread top-4
            const float* sqs = (const float*)(smem + SM_SQ);
#pragma unroll
            for (int mi = 0; mi < 2; mi++) {
                const int r0 = rm + wy * 32 + mi * 16 + g;
#pragma unroll
                for (int ni = 0; ni < 8; ni++) {
                    const int jl = jt * BN + wx * 64 + ni * 8 + tq * 2;
                    const float s0 = sqs[jl], s1 = sqs[jl + 1];
                    const int j0 = jb + jl, j1 = j0 + 1;
                    float k00 = fmaf(-2.f, acc[mi][ni][0], s0);
                    float k01 = fmaf(-2.f, acc[mi][ni][1], s1);
                    float k10 = fmaf(-2.f, acc[mi][ni][2], s0);
                    float k11 = fmaf(-2.f, acc[mi][ni][3], s1);
                    float* cv0 = tv[mi * 2 + 0]; int* ci0 = ti[mi * 2 + 0];
                    float* cv1 = tv[mi * 2 + 1]; int* ci1 = ti[mi * 2 + 1];
                    if (j0 != r0 && k00 < cv0[3]) ins4(k00, j0, cv0, ci0);
                    if (j1 != r0 && k01 < cv0[3]) ins4(k01, j1, cv0, ci0);
                    if (j0 != r0 + 8 && k10 < cv1[3]) ins4(k10, j0, cv1, ci1);
                    if (j1 != r0 + 8 && k11 < cv1[3]) ins4(k11, j1, cv1, ci1);
                }
            }
        }
        __syncthreads();
    }

    // ---- merge: dump per-thread top-4 lists, 32 entries per row ----
    // scr[row][slot]: row stride 32*8B = 256B; slot = wx*16 + tq*4 + q
#pragma unroll
    for (int m = 0; m < 4; m++) {
        int r = wy * 32 + (m >> 1) * 16 + (m & 1) * 8 + g;
        int slot = wx * 16 + tq * 4;
#pragma unroll
        for (int q = 0; q < 4; q++) {
            *(float*)(smem + SM_SCR + r * 256 + (slot + q) * 8) = tv[m][q];
            *(int*)(smem + SM_SCR + r * 256 + (slot + q) * 8 + 4) = ti[m][q];
        }
    }
    __syncthreads();

    if (tid < BM) {
        float cv[8]; int ci[8];
#pragma unroll
        for (int q = 0; q < 8; q++) { cv[q] = 3.0e38f; ci[q] = 0x7fffffff; }
#pragma unroll
        for (int sl = 0; sl < 32; sl++) {
            float v = *(const float*)(smem + SM_SCR + tid * 256 + sl * 8);
            int i = *(const int*)(smem + SM_SCR + tid * 256 + sl * 8 + 4);
            if (v < cv[7]) ins8(v, i, cv, ci);
        }
        int base = ((rm + tid) * JSPLIT + blockIdx.y) * NCAND;
#pragma unroll
        for (int q = 0; q < 8; q++) g_cand[base + q] = ci[q];
    }
}

// ==========================================================================
// 3) exact fp32 rescoring of 16 candidates -> final 4 neighbors
// ==========================================================================
__device__ __forceinline__ bool lessc(float va, int ia, float vb, int ib) {
    return (va < vb) || (va == vb && ia < ib);
}

__global__ void __launch_bounds__(256) rescore_kernel(const float* __restrict__ X) {
    int warp = (blockIdx.x * blockDim.x + threadIdx.x) >> 5;
    int lane = threadIdx.x & 31;
    if (warp >= T_PTS) return;

    float x[16];
    const float* xr = X + (size_t)warp * D_DIM;
#pragma unroll
    for (int q = 0; q < 16; q++) x[q] = xr[lane + q * 32];

    float kv[16]; int ki[16];
#pragma unroll 1
    for (int c = 0; c < 2 * NCAND; c++) {
        int j = g_cand[warp * (2 * NCAND) + c];
        const float* yr = X + (size_t)j * D_DIM;
        float s = 0.f;
#pragma unroll
        for (int q = 0; q < 16; q++) s = fmaf(x[q], yr[lane + q * 32], s);
#pragma unroll
        for (int o = 16; o; o >>= 1) s += __shfl_xor_sync(0xffffffffu, s, o);
        kv[c] = fmaf(-2.f, s, g_sq[j]);
        ki[c] = j;
    }

    if (lane == 0) {
#pragma unroll
        for (int r = 0; r < 4; r++) {
            float bv = kv[0]; int bi = ki[0];
#pragma unroll
            for (int c = 1; c < 16; c++)
                if (lessc(kv[c], ki[c], bv, bi)) { bv = kv[c]; bi = ki[c]; }
            g_neigh[warp * N_SYN + r] = bi;
#pragma unroll
            for (int c = 0; c < 16; c++)
                if (ki[c] == bi) kv[c] = 3.0e38f;
        }
    }
}

// ==========================================================================
// 4) gather + interpolate
// ==========================================================================
__global__ void interp_kernel(const float* __restrict__ X,
                              const float* __restrict__ gaps,
                              const int* __restrict__ nn_choice,
                              float* __restrict__ out) {
    const int gid = blockIdx.x * blockDim.x + threadIdx.x;
    const int row = gid >> 7;
    const int d4 = gid & 127;
    const int t = row >> 2;
    const float g = gaps[row];
    const int c = nn_choice[row];
    const int s = g_neigh[t * N_SYN + c];
    const float4* X4 = (const float4*)X;
    const float4 x = X4[t * 128 + d4];
    const float4 xs = X4[s * 128 + d4];
    float4 o;
    o.x = fmaf(g, xs.x - x.x, x.x);
    o.y = fmaf(g, xs.y - x.y, x.y);
    o.z = fmaf(g, xs.z - x.z, x.z);
    o.w = fmaf(g, xs.w - x.w, x.w);
    ((float4*)out)[gid] = o;
}

// ==========================================================================
extern "C" void kernel_launch(void* const* d_in, const int* in_sizes, int n_in,
                              void* d_out, int out_size) {
    (void)in_sizes; (void)n_in; (void)out_size;
    const float* X    = (const float*)d_in[0];
    const float* gaps = (const float*)d_in[1];
    const int*   nnc  = (const int*)d_in[2];
    float* out = (float*)d_out;

    cudaFuncSetAttribute(gemm_topk, cudaFuncAttributeMaxDynamicSharedMemorySize,
                         SMEM_TOTAL);

    sq_kernel<<<T_PTS / 8, 256>>>(X);
    prep_bf16<<<(T_PTS * D_DIM / 4) / 256, 256>>>(X);
    dim3 grid(T_PTS / BM, JSPLIT);
    gemm_topk<<<grid, 256, SMEM_TOTAL>>>();
    rescore_kernel<<<(T_PTS * 32) / 256, 256>>>(X);
    interp_kernel<<<(T_PTS * N_SYN * (D_DIM / 4)) / 256, 256>>>(X, gaps, nnc, out);
}

// round 9
// speedup vs baseline: 5.4891x; 1.0081x over previous
#include <cuda_runtime.h>
#include <cuda_bf16.h>
#include <cstdint>

// ==========================================================================
// Problem constants
// ==========================================================================
constexpr int T_PTS = 8192;
constexpr int D_DIM = 512;
constexpr int N_SYN = 4;

constexpr int BS = 128;                         // tile block size
constexpr int NBLK = T_PTS / BS;                // 64 row-blocks
constexpr int NPAIR = NBLK * (NBLK + 1) / 2;    // 2080 tile-pairs
constexpr int BK = 64;                          // K per stage (128B rows)
constexpr int KSTG = D_DIM / BK;                // 8 stages
constexpr int NC = 8;                           // final candidates per row

// SMEM layout
constexpr int SM_BUF = 0;                       // A0,B0,A1,B1: 4 x 16384
constexpr int SM_TR  = 65536;                   // 128 x 132 f32 transpose
constexpr int SM_SCR = SM_TR + 128 * 132 * 4;   // 133120; 32 KB scratch
constexpr int SM_SQI = SM_SCR + 32768;          // 165888
constexpr int SM_SQJ = SM_SQI + 512;            // 166400
constexpr int SMEM_TOTAL = SM_SQJ + 512;        // 166912

// ==========================================================================
// Device scratch
// ==========================================================================
__device__ float g_sq[T_PTS];
__device__ __nv_bfloat16 g_xbf[(size_t)T_PTS * D_DIM];
__device__ float g_pcv[(size_t)T_PTS * NBLK * 4];   // partial top-4 values
__device__ int   g_pci[(size_t)T_PTS * NBLK * 4];   // partial top-4 indices
__device__ int   g_cand[T_PTS * NC];
__device__ int   g_neigh[T_PTS * N_SYN];

// ==========================================================================
// PTX helpers (sm_80-compatible only; harness PTX target is plain sm_103)
// ==========================================================================
__device__ __forceinline__ uint32_t smem_u32(const void* p) {
    uint32_t a;
    asm("{ .reg .u64 t; cvta.to.shared.u64 t, %1; cvt.u32.u64 %0, t; }"
        : "=r"(a) : "l"(p));
    return a;
}
#define CP_ASYNC16(dst, src) \
    asm volatile("cp.async.cg.shared.global [%0], [%1], 16;" :: "r"(dst), "l"(src))
#define CP_COMMIT() asm volatile("cp.async.commit_group;" ::: "memory")
#define CP_WAIT(n) asm volatile("cp.async.wait_group %0;" :: "n"(n) : "memory")

// NON-trans ldmatrix: correct for K-major operands of mma .row.col
#define LDSM_X4(r0, r1, r2, r3, addr) \
    asm volatile("ldmatrix.sync.aligned.m8n8.x4.shared.b16 {%0,%1,%2,%3}, [%4];" \
                 : "=r"(r0), "=r"(r1), "=r"(r2), "=r"(r3) : "r"(addr))

#define MMA16816(d, a, b) \
    asm volatile("mma.sync.aligned.m16n8k16.row.col.f32.bf16.bf16.f32 " \
                 "{%0,%1,%2,%3}, {%4,%5,%6,%7}, {%8,%9}, {%0,%1,%2,%3};" \
                 : "+f"((d)[0]), "+f"((d)[1]), "+f"((d)[2]), "+f"((d)[3]) \
                 : "r"((a)[0]), "r"((a)[1]), "r"((a)[2]), "r"((a)[3]), \
                   "r"((b)[0]), "r"((b)[1]))

__device__ __forceinline__ uint32_t sw128(uint32_t off) {
    return off ^ ((off >> 3) & 0x70);
}

// ==========================================================================
// 0) bf16 copy of X
// ==========================================================================
__global__ void prep_bf16(const float* __restrict__ X) {
    int i = blockIdx.x * blockDim.x + threadIdx.x;
    float4 v = ((const float4*)X)[i];
    ((__nv_bfloat162*)g_xbf)[i * 2 + 0] = __floats2bfloat162_rn(v.x, v.y);
    ((__nv_bfloat162*)g_xbf)[i * 2 + 1] = __floats2bfloat162_rn(v.z, v.w);
}

// ==========================================================================
// 1) squared norms
// ==========================================================================
__global__ void sq_kernel(const float* __restrict__ X) {
    int warp = (blockIdx.x * blockDim.x + threadIdx.x) >> 5;
    int lane = threadIdx.x & 31;
    if (warp >= T_PTS) return;
    const float4* X4 = (const float4*)X;
    float s = 0.f;
#pragma unroll
    for (int q = 0; q < 4; q++) {
        float4 v = X4[warp * (D_DIM / 4) + q * 32 + lane];
        s = fmaf(v.x, v.x, s); s = fmaf(v.y, v.y, s);
        s = fmaf(v.z, v.z, s); s = fmaf(v.w, v.w, s);
    }
#pragma unroll
    for (int off = 16; off; off >>= 1) s += __shfl_xor_sync(0xffffffffu, s, off);
    if (lane == 0) g_sq[warp] = s;
}

// ==========================================================================
// small sorted-insert helpers
// ==========================================================================
__device__ __forceinline__ void ins4(float key, int j, float* cv, int* ci) {
    cv[3] = key; ci[3] = j;
#pragma unroll
    for (int q = 3; q > 0; q--) {
        if (cv[q] < cv[q - 1]) {
            float tv = cv[q]; cv[q] = cv[q - 1]; cv[q - 1] = tv;
            int t2 = ci[q]; ci[q] = ci[q - 1]; ci[q - 1] = t2;
        }
    }
}
__device__ __forceinline__ void ins8(float key, int j, float* cv, int* ci) {
    cv[7] = key; ci[7] = j;
#pragma unroll
    for (int q = 7; q > 0; q--) {
        if (cv[q] < cv[q - 1]) {
            float tv = cv[q]; cv[q] = cv[q - 1]; cv[q - 1] = tv;
            int t2 = ci[q]; ci[q] = ci[q - 1]; ci[q - 1] = t2;
        }
    }
}

// ==========================================================================
// 2) symmetric tile-pair GEMM: one CTA per (I,J), I<=J; emits top-4 partial
//    candidate lists in both directions (row-dir always, col-dir off-diag)
// ==========================================================================
__global__ void __launch_bounds__(256, 1) gemm_pair() {
    extern __shared__ char smem[];
    const uint32_t sb = smem_u32(smem);
    const int tid = threadIdx.x;
    const int wid = tid >> 5;
    const int lane = tid & 31;
    const int g = lane >> 2;
    const int tq = lane & 3;
    const int wy = wid & 3;         // m-band (32 rows)
    const int wx = wid >> 2;        // n-band (64 cols)

    // decode pair index -> (I, J), I <= J
    int p = blockIdx.x, I = 0;
    while (p >= NBLK - I) { p -= NBLK - I; I++; }
    const int J = I + p;

    // stage sq for both blocks
    if (tid < BS) *(float*)(smem + SM_SQI + tid * 4) = g_sq[I * BS + tid];
    else          *(float*)(smem + SM_SQJ + (tid - BS) * 4) = g_sq[J * BS + tid - BS];

    // chunk loader: A chunk (X_I rows, k-slice) + B chunk (X_J rows)
    auto load = [&](int s) {
        const uint32_t abuf = sb + SM_BUF + (uint32_t)(s & 1) * 32768u;
        const uint32_t bbuf = abuf + 16384u;
        const __nv_bfloat16* asrc = g_xbf + (size_t)(I * BS) * D_DIM + s * BK;
        const __nv_bfloat16* bsrc = g_xbf + (size_t)(J * BS) * D_DIM + s * BK;
#pragma unroll
        for (int it = 0; it < 4; it++) {
            int u = tid + it * 256;          // 1024 16B units per chunk
            int r = u >> 3, c = u & 7;
            uint32_t sw = sw128((uint32_t)r * 128u + (uint32_t)c * 16u);
            CP_ASYNC16(abuf + sw, asrc + (size_t)r * D_DIM + c * 8);
            CP_ASYNC16(bbuf + sw, bsrc + (size_t)r * D_DIM + c * 8);
        }
        CP_COMMIT();
    };

    load(0);

    float acc[2][8][4];
#pragma unroll
    for (int mi = 0; mi < 2; mi++)
#pragma unroll
        for (int ni = 0; ni < 8; ni++)
#pragma unroll
            for (int e = 0; e < 4; e++) acc[mi][ni][e] = 0.f;

#pragma unroll 1
    for (int s = 0; s < KSTG; s++) {
        if (s + 1 < KSTG) { load(s + 1); CP_WAIT(1); }
        else              { CP_WAIT(0); }
        __syncthreads();
        const uint32_t abuf = sb + SM_BUF + (uint32_t)(s & 1) * 32768u;
        const uint32_t bbuf = abuf + 16384u;

#pragma unroll
        for (int ks = 0; ks < 4; ks++) {
            uint32_t a[2][4];
#pragma unroll
            for (int mi = 0; mi < 2; mi++) {
                int r = wy * 32 + mi * 16 + (lane & 15);
                int ke = ks * 16 + ((lane & 16) >> 1);
                LDSM_X4(a[mi][0], a[mi][1], a[mi][2], a[mi][3],
                        abuf + sw128((uint32_t)r * 128u + (uint32_t)ke * 2u));
            }
            uint32_t b[8][2];
#pragma unroll
            for (int nb = 0; nb < 4; nb++) {
                int jr = wx * 64 + nb * 16 + ((lane & 16) >> 1) + (lane & 7);
                int ke = ks * 16 + (lane & 8);
                LDSM_X4(b[2 * nb][0], b[2 * nb][1],
                        b[2 * nb + 1][0], b[2 * nb + 1][1],
                        bbuf + sw128((uint32_t)jr * 128u + (uint32_t)ke * 2u));
            }
#pragma unroll
            for (int mi = 0; mi < 2; mi++)
#pragma unroll
                for (int ni = 0; ni < 8; ni++)
                    MMA16816(acc[mi][ni], a[mi], b[ni]);
        }
        __syncthreads();
    }

    // ---------------- epilogue: row direction (rows of I over cols of J) ----
    {
        float tv[4][4]; int ti[4][4];
#pragma unroll
        for (int m = 0; m < 4; m++)
#pragma unroll
            for (int q = 0; q < 4; q++) { tv[m][q] = 3.0e38f; ti[m][q] = 0x7fffffff; }

        const float* sqJ = (const float*)(smem + SM_SQJ);
#pragma unroll
        for (int mi = 0; mi < 2; mi++) {
            const int r0 = I * BS + wy * 32 + mi * 16 + g;     // global row (o=0)
#pragma unroll
            for (int ni = 0; ni < 8; ni++) {
                const int jl = wx * 64 + ni * 8 + tq * 2;
                const float s0 = sqJ[jl], s1 = sqJ[jl + 1];
                const int j0 = J * BS + jl, j1 = j0 + 1;
                float k00 = fmaf(-2.f, acc[mi][ni][0], s0);
                float k01 = fmaf(-2.f, acc[mi][ni][1], s1);
                float k10 = fmaf(-2.f, acc[mi][ni][2], s0);
                float k11 = fmaf(-2.f, acc[mi][ni][3], s1);
                float* cv0 = tv[mi * 2 + 0]; int* ci0 = ti[mi * 2 + 0];
                float* cv1 = tv[mi * 2 + 1]; int* ci1 = ti[mi * 2 + 1];
                if (j0 != r0 && k00 < cv0[3]) ins4(k00, j0, cv0, ci0);
                if (j1 != r0 && k01 < cv0[3]) ins4(k01, j1, cv0, ci0);
                if (j0 != r0 + 8 && k10 < cv1[3]) ins4(k10, j0, cv1, ci1);
                if (j1 != r0 + 8 && k11 < cv1[3]) ins4(k11, j1, cv1, ci1);
            }
        }
        // dump 8 thread-lists per row (wx,tq) -> 32 entries, row stride 256B
#pragma unroll
        for (int m = 0; m < 4; m++) {
            int r = wy * 32 + (m >> 1) * 16 + (m & 1) * 8 + g;
            int slot = wx * 16 + tq * 4;
#pragma unroll
            for (int q = 0; q < 4; q++) {
                *(float*)(smem + SM_SCR + r * 256 + (slot + q) * 8) = tv[m][q];
                *(int*)(smem + SM_SCR + r * 256 + (slot + q) * 8 + 4) = ti[m][q];
            }
        }
    }
    __syncthreads();
    if (tid < BS) {
        float cv[4]; int ci[4];
#pragma unroll
        for (int q = 0; q < 4; q++) { cv[q] = 3.0e38f; ci[q] = 0x7fffffff; }
#pragma unroll
        for (int sl = 0; sl < 32; sl++) {
            float v = *(const float*)(smem + SM_SCR + tid * 256 + sl * 8);
            int i = *(const int*)(smem + SM_SCR + tid * 256 + sl * 8 + 4);
            if (v < cv[3]) ins4(v, i, cv, ci);
        }
        size_t base = ((size_t)(I * BS + tid) * NBLK + J) * 4;
#pragma unroll
        for (int q = 0; q < 4; q++) { g_pcv[base + q] = cv[q]; g_pci[base + q] = ci[q]; }
    }

    // ---------------- epilogue: column direction (rows of J over rows of I) --
    if (I != J) {
        __syncthreads();
        float* tr = (float*)(smem + SM_TR);
        // conflict-free transposed store: tr[n][m], row pitch 132 floats
#pragma unroll
        for (int mi = 0; mi < 2; mi++)
#pragma unroll
            for (int ni = 0; ni < 8; ni++)
#pragma unroll
                for (int e = 0; e < 4; e++) {
                    int m = wy * 32 + mi * 16 + g + 8 * (e >> 1);
                    int n = wx * 64 + ni * 8 + tq * 2 + (e & 1);
                    tr[n * 132 + m] = acc[mi][ni][e];
                }
        __syncthreads();

        const float* sqI = (const float*)(smem + SM_SQI);
        const int c = tid >> 1, h = tid & 1;     // 2 threads per column
        float cv[4]; int ci[4];
#pragma unroll
        for (int q = 0; q < 4; q++) { cv[q] = 3.0e38f; ci[q] = 0x7fffffff; }
#pragma unroll 1
        for (int m = h * 64; m < h * 64 + 64; m++) {
            float key = fmaf(-2.f, tr[c * 132 + m], sqI[m]);
            if (key < cv[3]) ins4(key, I * BS + m, cv, ci);
        }
        // dump 2 half-lists per column (8 entries), then h==0 merges
#pragma unroll
        for (int q = 0; q < 4; q++) {
            *(float*)(smem + SM_SCR + c * 64 + (h * 4 + q) * 8) = cv[q];
            *(int*)(smem + SM_SCR + c * 64 + (h * 4 + q) * 8 + 4) = ci[q];
        }
        __syncthreads();
        if (h == 0) {
#pragma unroll
            for (int q = 0; q < 4; q++) {
                float v = *(const float*)(smem + SM_SCR + c * 64 + (4 + q) * 8);
                int i = *(const int*)(smem + SM_SCR + c * 64 + (4 + q) * 8 + 4);
                if (v < cv[3]) ins4(v, i, cv, ci);
            }
            size_t base = ((size_t)(J * BS + c) * NBLK + I) * 4;
#pragma unroll
            for (int q = 0; q < 4; q++) { g_pcv[base + q] = cv[q]; g_pci[base + q] = ci[q]; }
        }
    }
}

// ==========================================================================
// 3) merge 64 partial lists per row -> global top-8 candidates (warp/row)
// ==========================================================================
__global__ void __launch_bounds__(256) merge_cand() {
    int row = (blockIdx.x * blockDim.x + threadIdx.x) >> 5;
    int lane = threadIdx.x & 31;
    if (row >= T_PTS) return;

    float cv[8]; int ci[8];
#pragma unroll
    for (int q = 0; q < 8; q++) { cv[q] = 3.0e38f; ci[q] = 0x7fffffff; }

    const size_t base = (size_t)row * (NBLK * 4);
#pragma unroll
    for (int q = 0; q < 8; q++) {
        int e = lane + 32 * q;                   // 256 entries, coalesced
        float v = g_pcv[base + e];
        int i = g_pci[base + e];
        if (v < cv[7]) ins8(v, i, cv, ci);
    }
    // butterfly merge (disjoint sources each round -> no duplicates)
#pragma unroll
    for (int mask = 1; mask <= 16; mask <<= 1) {
        float ov[8]; int oi[8];
#pragma unroll
        for (int q = 0; q < 8; q++) {
            ov[q] = __shfl_xor_sync(0xffffffffu, cv[q], mask);
            oi[q] = __shfl_xor_sync(0xffffffffu, ci[q], mask);
        }
#pragma unroll
        for (int q = 0; q < 8; q++)
            if (ov[q] < cv[7]) ins8(ov[q], oi[q], cv, ci);
    }
    if (lane == 0) {
#pragma unroll
        for (int q = 0; q < 8; q++) g_cand[row * NC + q] = ci[q];
    }
}

// ==========================================================================
// 4) exact fp32 rescoring of 8 candidates -> final 4 neighbors
// ==========================================================================
__device__ __forceinline__ bool lessc(float va, int ia, float vb, int ib) {
    return (va < vb) || (va == vb && ia < ib);
}

__global__ void __launch_bounds__(256) rescore_kernel(const float* __restrict__ X) {
    int warp = (blockIdx.x * blockDim.x + threadIdx.x) >> 5;
    int lane = threadIdx.x & 31;
    if (warp >= T_PTS) return;

    float x[16];
    const float* xr = X + (size_t)warp * D_DIM;
#pragma unroll
    for (int q = 0; q < 16; q++) x[q] = xr[lane + q * 32];

    float kv[NC]; int ki[NC];
#pragma unroll 1
    for (int c = 0; c < NC; c++) {
        int j = g_cand[warp * NC + c];
        const float* yr = X + (size_t)j * D_DIM;
        float s = 0.f;
#pragma unroll
        for (int q = 0; q < 16; q++) s = fmaf(x[q], yr[lane + q * 32], s);
#pragma unroll
        for (int o = 16; o; o >>= 1) s += __shfl_xor_sync(0xffffffffu, s, o);
        kv[c] = fmaf(-2.f, s, g_sq[j]);
        ki[c] = j;
    }

    if (lane == 0) {
#pragma unroll
        for (int r = 0; r < 4; r++) {
            float bv = kv[0]; int bi = ki[0];
#pragma unroll
            for (int c = 1; c < NC; c++)
                if (lessc(kv[c], ki[c], bv, bi)) { bv = kv[c]; bi = ki[c]; }
            g_neigh[warp * N_SYN + r] = bi;
#pragma unroll
            for (int c = 0; c < NC; c++)
                if (ki[c] == bi) kv[c] = 3.0e38f;
        }
    }
}

// ==========================================================================
// 5) gather + interpolate
// ==========================================================================
__global__ void interp_kernel(const float* __restrict__ X,
                              const float* __restrict__ gaps,
                              const int* __restrict__ nn_choice,
                              float* __restrict__ out) {
    const int gid = blockIdx.x * blockDim.x + threadIdx.x;
    const int row = gid >> 7;
    const int d4 = gid & 127;
    const int t = row >> 2;
    const float g = gaps[row];
    const int c = nn_choice[row];
    const int s = g_neigh[t * N_SYN + c];
    const float4* X4 = (const float4*)X;
    const float4 x = X4[t * 128 + d4];
    const float4 xs = X4[s * 128 + d4];
    float4 o;
    o.x = fmaf(g, xs.x - x.x, x.x);
    o.y = fmaf(g, xs.y - x.y, x.y);
    o.z = fmaf(g, xs.z - x.z, x.z);
    o.w = fmaf(g, xs.w - x.w, x.w);
    ((float4*)out)[gid] = o;
}

// ==========================================================================
extern "C" void kernel_launch(void* const* d_in, const int* in_sizes, int n_in,
                              void* d_out, int out_size) {
    (void)in_sizes; (void)n_in; (void)out_size;
    const float* X    = (const float*)d_in[0];
    const float* gaps = (const float*)d_in[1];
    const int*   nnc  = (const int*)d_in[2];
    float* out = (float*)d_out;

    cudaFuncSetAttribute(gemm_pair, cudaFuncAttributeMaxDynamicSharedMemorySize,
                         SMEM_TOTAL);

    sq_kernel<<<T_PTS / 8, 256>>>(X);
    prep_bf16<<<(T_PTS * D_DIM / 4) / 256, 256>>>(X);
    gemm_pair<<<NPAIR, 256, SMEM_TOTAL>>>();
    merge_cand<<<T_PTS / 8, 256>>>();
    rescore_kernel<<<(T_PTS * 32) / 256, 256>>>(X);
    interp_kernel<<<(T_PTS * N_SYN * (D_DIM / 4)) / 256, 256>>>(X, gaps, nnc, out);
}